// round 8
// baseline (speedup 1.0000x reference)
#include <cuda_runtime.h>
#include <cstdint>

#define N_NODES 100000
#define N_EDGES 1600000
#define DIM 128
#define SCAN_B 1024
#define N_SCAN_BLOCKS ((N_NODES + SCAN_B - 1) / SCAN_B)   // 98

// Static device scratch (zero-initialized at module load; gather re-zeroes
// g_cnt / g_scan_st each call for the next replay).
__device__ float              g_h[(size_t)N_NODES * DIM];   // 51.2 MB
__device__ int                g_cnt[N_NODES];
__device__ int                g_off[N_NODES + 1];
__device__ int                g_cursor[N_NODES];
__device__ unsigned long long g_scan_st[N_SCAN_BLOCKS];     // (flag<<32)|sum; 1=agg, 2=prefix
__device__ uint2              g_edge[N_EDGES];              // (col, val-bits)

// ---------------------------------------------------------------------------
// Kernel 1: h = x@W + b. Plain-FFMA (measured at the fp32 FMA-pipe floor).
// Tile 64 rows x 128 cols per 256-thread block; thread = 8 rows x 4 cols.
// ---------------------------------------------------------------------------
#define TM 64
__global__ __launch_bounds__(256) void gemm_kernel(
    const float* __restrict__ x, const float* __restrict__ W,
    const float* __restrict__ b)
{
    __shared__ float Xs[TM][DIM];   // 32 KB

    const int tid = threadIdx.x;
    const int tx  = tid & 31;
    const int ty  = tid >> 5;
    const int block_row = blockIdx.x * TM;

    {
        const float4* xg = reinterpret_cast<const float4*>(x) + (size_t)block_row * (DIM / 4);
        float4* xs4 = reinterpret_cast<float4*>(&Xs[0][0]);
        #pragma unroll
        for (int i = 0; i < 8; i++) {
            int idx = tid + i * 256;
            int row = block_row + (idx >> 5);
            xs4[idx] = (row < N_NODES) ? xg[idx] : make_float4(0.f, 0.f, 0.f, 0.f);
        }
    }
    __syncthreads();

    float acc[8][4];
    {
        float4 bv = reinterpret_cast<const float4*>(b)[tx];
        #pragma unroll
        for (int r = 0; r < 8; r++) {
            acc[r][0] = bv.x; acc[r][1] = bv.y; acc[r][2] = bv.z; acc[r][3] = bv.w;
        }
    }

    const float4* W4 = reinterpret_cast<const float4*>(W);
    #pragma unroll 4
    for (int k = 0; k < DIM; k++) {
        float4 wv = __ldg(W4 + k * (DIM / 4) + tx);
        #pragma unroll
        for (int r = 0; r < 8; r++) {
            float xv = Xs[ty * 8 + r][k];
            acc[r][0] += xv * wv.x;
            acc[r][1] += xv * wv.y;
            acc[r][2] += xv * wv.z;
            acc[r][3] += xv * wv.w;
        }
    }

    #pragma unroll
    for (int r = 0; r < 8; r++) {
        int row = block_row + ty * 8 + r;
        if (row < N_NODES) {
            reinterpret_cast<float4*>(g_h + (size_t)row * DIM)[tx] =
                make_float4(acc[r][0], acc[r][1], acc[r][2], acc[r][3]);
        }
    }
}

// ---------------------------------------------------------------------------
// Kernel 2: in-degree histogram. 4 edges/thread, int4 load, no-return REDs.
// ---------------------------------------------------------------------------
__global__ void hist_kernel(const int* __restrict__ rows) {
    int t = blockIdx.x * blockDim.x + threadIdx.x;
    if (t < N_EDGES / 4) {
        int4 r4 = __ldg(reinterpret_cast<const int4*>(rows) + t);
        atomicAdd(&g_cnt[r4.x], 1);
        atomicAdd(&g_cnt[r4.y], 1);
        atomicAdd(&g_cnt[r4.z], 1);
        atomicAdd(&g_cnt[r4.w], 1);
    }
}

// ---------------------------------------------------------------------------
// Kernel 3: single-pass exclusive scan, warp-parallel decoupled lookback.
// ---------------------------------------------------------------------------
__global__ __launch_bounds__(SCAN_B) void scan_kernel() {
    __shared__ int s_warp[32];
    __shared__ int s_excl;

    const int b    = blockIdx.x;
    const int lane = threadIdx.x & 31;
    const int wid  = threadIdx.x >> 5;
    const int i    = b * SCAN_B + threadIdx.x;

    if (i == 0) g_off[N_NODES] = N_EDGES;

    int v = (i < N_NODES) ? g_cnt[i] : 0;

    int incl = v;
    #pragma unroll
    for (int d = 1; d < 32; d <<= 1) {
        int t = __shfl_up_sync(0xffffffffu, incl, d);
        if (lane >= d) incl += t;
    }
    if (lane == 31) s_warp[wid] = incl;
    __syncthreads();

    if (wid == 0) {
        int ws = s_warp[lane];
        int wincl = ws;
        #pragma unroll
        for (int d = 1; d < 32; d <<= 1) {
            int t = __shfl_up_sync(0xffffffffu, wincl, d);
            if (lane >= d) wincl += t;
        }
        s_warp[lane] = wincl - ws;
        int total = __shfl_sync(0xffffffffu, wincl, 31);

        if (lane == 0)
            atomicExch(&g_scan_st[b],
                       ((b == 0 ? 2ull : 1ull) << 32) | (unsigned)total);

        int excl = 0;
        if (b > 0) {
            int base = b;
            while (true) {
                int j = base - 1 - lane;
                int flag;
                unsigned agg = 0;
                if (j >= 0) {
                    unsigned long long s;
                    do {
                        s = atomicAdd(&g_scan_st[j], 0ull);
                        flag = (int)(s >> 32);
                        if (!flag) __nanosleep(32);
                    } while (!flag);
                    agg = (unsigned)s;
                } else {
                    flag = 2;
                }
                unsigned ball = __ballot_sync(0xffffffffu, flag == 2);
                int val = (int)agg;
                if (ball) {
                    int first = __ffs(ball) - 1;
                    if (lane > first) val = 0;
                }
                #pragma unroll
                for (int d = 16; d; d >>= 1)
                    val += __shfl_xor_sync(0xffffffffu, val, d);
                excl += val;
                if (ball) break;
                base -= 32;
            }
            if (lane == 0)
                atomicExch(&g_scan_st[b], (2ull << 32) | (unsigned)(excl + total));
        }
        if (lane == 0) s_excl = excl;
    }
    __syncthreads();

    if (i < N_NODES) {
        int o = s_excl + s_warp[wid] + (incl - v);
        g_off[i]    = o;
        g_cursor[i] = o;
    }
}

// ---------------------------------------------------------------------------
// Kernel 4: fill packed edge list (col, val) per destination node.
// ---------------------------------------------------------------------------
__global__ void fill_kernel(const int* __restrict__ rows,
                            const int* __restrict__ cols,
                            const float* __restrict__ vals) {
    int e = blockIdx.x * blockDim.x + threadIdx.x;
    if (e < N_EDGES) {
        int pos = atomicAdd(&g_cursor[rows[e]], 1);
        g_edge[pos] = make_uint2((unsigned)cols[e], __float_as_uint(vals[e]));
    }
}

// ---------------------------------------------------------------------------
// Kernel 5: pull-gather, one warp per node, unroll-4 for MLP.
// Prologue re-zeroes g_cnt / g_scan_st for the NEXT call.
// ---------------------------------------------------------------------------
__global__ __launch_bounds__(256) void gather_kernel(float* __restrict__ out) {
    {
        int gt = blockIdx.x * 256 + threadIdx.x;
        if (gt < N_NODES) g_cnt[gt] = 0;
        if (gt < N_SCAN_BLOCKS) g_scan_st[gt] = 0ull;
    }

    const int node = (blockIdx.x * 256 + threadIdx.x) >> 5;
    if (node >= N_NODES) return;
    const int lane = threadIdx.x & 31;

    const int beg = __ldg(&g_off[node]);
    const int end = __ldg(&g_off[node + 1]);

    const float4* h4 = reinterpret_cast<const float4*>(g_h);
    float4 acc = make_float4(0.f, 0.f, 0.f, 0.f);

    int i = beg;
    for (; i + 3 < end; i += 4) {
        uint2 e0 = __ldg(&g_edge[i]);
        uint2 e1 = __ldg(&g_edge[i + 1]);
        uint2 e2 = __ldg(&g_edge[i + 2]);
        uint2 e3 = __ldg(&g_edge[i + 3]);
        float4 a0 = __ldg(h4 + (size_t)e0.x * 32 + lane);
        float4 a1 = __ldg(h4 + (size_t)e1.x * 32 + lane);
        float4 a2 = __ldg(h4 + (size_t)e2.x * 32 + lane);
        float4 a3 = __ldg(h4 + (size_t)e3.x * 32 + lane);
        float v0 = __uint_as_float(e0.y);
        float v1 = __uint_as_float(e1.y);
        float v2 = __uint_as_float(e2.y);
        float v3 = __uint_as_float(e3.y);
        acc.x += v0 * a0.x; acc.y += v0 * a0.y; acc.z += v0 * a0.z; acc.w += v0 * a0.w;
        acc.x += v1 * a1.x; acc.y += v1 * a1.y; acc.z += v1 * a1.z; acc.w += v1 * a1.w;
        acc.x += v2 * a2.x; acc.y += v2 * a2.y; acc.z += v2 * a2.z; acc.w += v2 * a2.w;
        acc.x += v3 * a3.x; acc.y += v3 * a3.y; acc.z += v3 * a3.z; acc.w += v3 * a3.w;
    }
    for (; i < end; i++) {
        uint2 e0 = __ldg(&g_edge[i]);
        float4 a0 = __ldg(h4 + (size_t)e0.x * 32 + lane);
        float v0 = __uint_as_float(e0.y);
        acc.x += v0 * a0.x; acc.y += v0 * a0.y; acc.z += v0 * a0.z; acc.w += v0 * a0.w;
    }

    reinterpret_cast<float4*>(out)[(size_t)node * 32 + lane] = acc;
}

// ---------------------------------------------------------------------------
extern "C" void kernel_launch(void* const* d_in, const int* in_sizes, int n_in,
                              void* d_out, int out_size)
{
    const float* x    = (const float*)d_in[0];
    const float* W    = (const float*)d_in[1];
    const float* b    = (const float*)d_in[2];
    const float* vals = (const float*)d_in[3];
    const int*   rows = (const int*)d_in[4];
    const int*   cols = (const int*)d_in[5];
    float* out = (float*)d_out;

    const int EB = (N_EDGES + 255) / 256;

    // 1. GEMM
    gemm_kernel<<<(N_NODES + TM - 1) / TM, 256>>>(x, W, b);
    // 2. in-degree histogram
    hist_kernel<<<(N_EDGES / 4 + 255) / 256, 256>>>(rows);
    // 3. single-pass exclusive scan (warp-parallel lookback)
    scan_kernel<<<N_SCAN_BLOCKS, SCAN_B>>>();
    // 4. CSR edge fill
    fill_kernel<<<EB, 256>>>(rows, cols, vals);
    // 5. pull-gather (+ state reset for next replay)
    gather_kernel<<<(N_NODES * 32 + 255) / 256, 256>>>(out);
}

// round 16
// speedup vs baseline: 1.4372x; 1.4372x over previous
#include <cuda_runtime.h>
#include <cstdint>

#define N_NODES 100000
#define N_EDGES 1600000
#define DIM 128
#define SCAN_B 1024
#define N_SCAN_BLOCKS ((N_NODES + SCAN_B - 1) / SCAN_B)   // 98

// Static device scratch (zero-initialized at module load; gather re-zeroes
// g_cnt / g_scan_st each call for the next replay).
__device__ float              g_h[(size_t)N_NODES * DIM];   // 51.2 MB
__device__ int                g_cnt[N_NODES];
__device__ int                g_off[N_NODES + 1];
__device__ int                g_cursor[N_NODES];
__device__ unsigned long long g_scan_st[N_SCAN_BLOCKS];     // (flag<<32)|sum; 1=agg, 2=prefix
__device__ uint2              g_edge[N_EDGES];              // (col, val-bits)

// ---------------------------------------------------------------------------
// Kernel 1: h = x@W + b. Plain-FFMA (measured at the fp32 FMA-pipe floor).
// Tile 64 rows x 128 cols per 256-thread block; thread = 8 rows x 4 cols.
// ---------------------------------------------------------------------------
#define TM 64
__global__ __launch_bounds__(256) void gemm_kernel(
    const float* __restrict__ x, const float* __restrict__ W,
    const float* __restrict__ b)
{
    __shared__ float Xs[TM][DIM];   // 32 KB

    const int tid = threadIdx.x;
    const int tx  = tid & 31;
    const int ty  = tid >> 5;
    const int block_row = blockIdx.x * TM;

    {
        const float4* xg = reinterpret_cast<const float4*>(x) + (size_t)block_row * (DIM / 4);
        float4* xs4 = reinterpret_cast<float4*>(&Xs[0][0]);
        #pragma unroll
        for (int i = 0; i < 8; i++) {
            int idx = tid + i * 256;
            int row = block_row + (idx >> 5);
            xs4[idx] = (row < N_NODES) ? xg[idx] : make_float4(0.f, 0.f, 0.f, 0.f);
        }
    }
    __syncthreads();

    float acc[8][4];
    {
        float4 bv = reinterpret_cast<const float4*>(b)[tx];
        #pragma unroll
        for (int r = 0; r < 8; r++) {
            acc[r][0] = bv.x; acc[r][1] = bv.y; acc[r][2] = bv.z; acc[r][3] = bv.w;
        }
    }

    const float4* W4 = reinterpret_cast<const float4*>(W);
    #pragma unroll 4
    for (int k = 0; k < DIM; k++) {
        float4 wv = __ldg(W4 + k * (DIM / 4) + tx);
        #pragma unroll
        for (int r = 0; r < 8; r++) {
            float xv = Xs[ty * 8 + r][k];
            acc[r][0] += xv * wv.x;
            acc[r][1] += xv * wv.y;
            acc[r][2] += xv * wv.z;
            acc[r][3] += xv * wv.w;
        }
    }

    #pragma unroll
    for (int r = 0; r < 8; r++) {
        int row = block_row + ty * 8 + r;
        if (row < N_NODES) {
            reinterpret_cast<float4*>(g_h + (size_t)row * DIM)[tx] =
                make_float4(acc[r][0], acc[r][1], acc[r][2], acc[r][3]);
        }
    }
}

// ---------------------------------------------------------------------------
// Kernel 2: in-degree histogram. 4 edges/thread, int4 load, no-return REDs.
// ---------------------------------------------------------------------------
__global__ void hist_kernel(const int* __restrict__ rows) {
    int t = blockIdx.x * blockDim.x + threadIdx.x;
    if (t < N_EDGES / 4) {
        int4 r4 = __ldg(reinterpret_cast<const int4*>(rows) + t);
        atomicAdd(&g_cnt[r4.x], 1);
        atomicAdd(&g_cnt[r4.y], 1);
        atomicAdd(&g_cnt[r4.z], 1);
        atomicAdd(&g_cnt[r4.w], 1);
    }
}

// ---------------------------------------------------------------------------
// Kernel 3: single-pass exclusive scan, warp-parallel decoupled lookback.
// ---------------------------------------------------------------------------
__global__ __launch_bounds__(SCAN_B) void scan_kernel() {
    __shared__ int s_warp[32];
    __shared__ int s_excl;

    const int b    = blockIdx.x;
    const int lane = threadIdx.x & 31;
    const int wid  = threadIdx.x >> 5;
    const int i    = b * SCAN_B + threadIdx.x;

    if (i == 0) g_off[N_NODES] = N_EDGES;

    int v = (i < N_NODES) ? g_cnt[i] : 0;

    int incl = v;
    #pragma unroll
    for (int d = 1; d < 32; d <<= 1) {
        int t = __shfl_up_sync(0xffffffffu, incl, d);
        if (lane >= d) incl += t;
    }
    if (lane == 31) s_warp[wid] = incl;
    __syncthreads();

    if (wid == 0) {
        int ws = s_warp[lane];
        int wincl = ws;
        #pragma unroll
        for (int d = 1; d < 32; d <<= 1) {
            int t = __shfl_up_sync(0xffffffffu, wincl, d);
            if (lane >= d) wincl += t;
        }
        s_warp[lane] = wincl - ws;
        int total = __shfl_sync(0xffffffffu, wincl, 31);

        if (lane == 0)
            atomicExch(&g_scan_st[b],
                       ((b == 0 ? 2ull : 1ull) << 32) | (unsigned)total);

        int excl = 0;
        if (b > 0) {
            int base = b;
            while (true) {
                int j = base - 1 - lane;
                int flag;
                unsigned agg = 0;
                if (j >= 0) {
                    unsigned long long s;
                    do {
                        s = atomicAdd(&g_scan_st[j], 0ull);
                        flag = (int)(s >> 32);
                        if (!flag) __nanosleep(32);
                    } while (!flag);
                    agg = (unsigned)s;
                } else {
                    flag = 2;
                }
                unsigned ball = __ballot_sync(0xffffffffu, flag == 2);
                int val = (int)agg;
                if (ball) {
                    int first = __ffs(ball) - 1;
                    if (lane > first) val = 0;
                }
                #pragma unroll
                for (int d = 16; d; d >>= 1)
                    val += __shfl_xor_sync(0xffffffffu, val, d);
                excl += val;
                if (ball) break;
                base -= 32;
            }
            if (lane == 0)
                atomicExch(&g_scan_st[b], (2ull << 32) | (unsigned)(excl + total));
        }
        if (lane == 0) s_excl = excl;
    }
    __syncthreads();

    if (i < N_NODES) {
        int o = s_excl + s_warp[wid] + (incl - v);
        g_off[i]    = o;
        g_cursor[i] = o;
    }
}

// ---------------------------------------------------------------------------
// Kernel 4: fill packed edge list (col, val) per destination node.
// ---------------------------------------------------------------------------
__global__ void fill_kernel(const int* __restrict__ rows,
                            const int* __restrict__ cols,
                            const float* __restrict__ vals) {
    int e = blockIdx.x * blockDim.x + threadIdx.x;
    if (e < N_EDGES) {
        int pos = atomicAdd(&g_cursor[rows[e]], 1);
        g_edge[pos] = make_uint2((unsigned)cols[e], __float_as_uint(vals[e]));
    }
}

// ---------------------------------------------------------------------------
// Kernel 5: pull-gather, one warp per node, unroll-2 (measured best config).
// Prologue re-zeroes g_cnt / g_scan_st for the NEXT call.
// ---------------------------------------------------------------------------
__global__ __launch_bounds__(256) void gather_kernel(float* __restrict__ out) {
    {
        int gt = blockIdx.x * 256 + threadIdx.x;
        if (gt < N_NODES) g_cnt[gt] = 0;
        if (gt < N_SCAN_BLOCKS) g_scan_st[gt] = 0ull;
    }

    const int node = (blockIdx.x * 256 + threadIdx.x) >> 5;
    if (node >= N_NODES) return;
    const int lane = threadIdx.x & 31;

    const int beg = __ldg(&g_off[node]);
    const int end = __ldg(&g_off[node + 1]);

    const float4* h4 = reinterpret_cast<const float4*>(g_h);
    float4 acc = make_float4(0.f, 0.f, 0.f, 0.f);

    int i = beg;
    for (; i + 1 < end; i += 2) {
        uint2 e0 = __ldg(&g_edge[i]);
        uint2 e1 = __ldg(&g_edge[i + 1]);
        float4 a0 = __ldg(h4 + (size_t)e0.x * 32 + lane);
        float4 a1 = __ldg(h4 + (size_t)e1.x * 32 + lane);
        float v0 = __uint_as_float(e0.y);
        float v1 = __uint_as_float(e1.y);
        acc.x += v0 * a0.x; acc.y += v0 * a0.y;
        acc.z += v0 * a0.z; acc.w += v0 * a0.w;
        acc.x += v1 * a1.x; acc.y += v1 * a1.y;
        acc.z += v1 * a1.z; acc.w += v1 * a1.w;
    }
    if (i < end) {
        uint2 e0 = __ldg(&g_edge[i]);
        float4 a0 = __ldg(h4 + (size_t)e0.x * 32 + lane);
        float v0 = __uint_as_float(e0.y);
        acc.x += v0 * a0.x; acc.y += v0 * a0.y;
        acc.z += v0 * a0.z; acc.w += v0 * a0.w;
    }

    reinterpret_cast<float4*>(out)[(size_t)node * 32 + lane] = acc;
}

// ---------------------------------------------------------------------------
extern "C" void kernel_launch(void* const* d_in, const int* in_sizes, int n_in,
                              void* d_out, int out_size)
{
    const float* x    = (const float*)d_in[0];
    const float* W    = (const float*)d_in[1];
    const float* b    = (const float*)d_in[2];
    const float* vals = (const float*)d_in[3];
    const int*   rows = (const int*)d_in[4];
    const int*   cols = (const int*)d_in[5];
    float* out = (float*)d_out;

    const int EB = (N_EDGES + 255) / 256;

    // 1. GEMM
    gemm_kernel<<<(N_NODES + TM - 1) / TM, 256>>>(x, W, b);
    // 2. in-degree histogram
    hist_kernel<<<(N_EDGES / 4 + 255) / 256, 256>>>(rows);
    // 3. single-pass exclusive scan (warp-parallel lookback)
    scan_kernel<<<N_SCAN_BLOCKS, SCAN_B>>>();
    // 4. CSR edge fill
    fill_kernel<<<EB, 256>>>(rows, cols, vals);
    // 5. pull-gather (+ state reset for next replay)
    gather_kernel<<<(N_NODES * 32 + 255) / 256, 256>>>(out);
}